// round 2
// baseline (speedup 1.0000x reference)
#include <cuda_runtime.h>
#include <cstdint>
#include <math.h>

#define T_  1024
#define H_  2048
#define I_  1408
#define E_  16
#define IS_ 2816
#define TK  4
#define NA  (T_*TK)   // 4096 token-expert assignments

// ---------------- scratch (device globals; no allocation in kernel_launch) -------------
__device__ float g_GU  [(size_t)NA * (2*I_)];   // routed gate_up output [4096, 2816]
__device__ float g_ACT [(size_t)NA * I_];       // routed activation     [4096, 1408]
__device__ float g_ROUT[(size_t)NA * H_];       // routed down output    [4096, 2048]
__device__ float g_SGU [(size_t)T_ * (2*IS_)];  // shared gate_up        [1024, 5632]
__device__ float g_SACT[(size_t)T_ * IS_];      // shared activation     [1024, 2816]
__device__ float g_SH  [(size_t)T_ * H_];       // shared down output    [1024, 2048]
__device__ int   g_eid [NA];                    // expert id per assignment
__device__ float g_tw  [NA];                    // routing weight per assignment
__device__ int   g_cnt [E_];                    // tokens per expert
__device__ int   g_rows[E_ * T_];               // assignment ids grouped by expert

// ---------------- helpers -------------------------------------------------------------
__device__ __forceinline__ uint32_t f2tf32(float x) {
    uint32_t r; asm("cvt.rna.tf32.f32 %0, %1;" : "=r"(r) : "f"(x)); return r;
}
__device__ __forceinline__ void mma8(float* c, const uint32_t* a, const uint32_t* b) {
    asm volatile(
        "mma.sync.aligned.m16n8k8.row.col.f32.tf32.tf32.f32 "
        "{%0,%1,%2,%3}, {%4,%5,%6,%7}, {%8,%9}, {%0,%1,%2,%3};\n"
        : "+f"(c[0]), "+f"(c[1]), "+f"(c[2]), "+f"(c[3])
        : "r"(a[0]), "r"(a[1]), "r"(a[2]), "r"(a[3]), "r"(b[0]), "r"(b[1]));
}
__device__ __forceinline__ void cp16(void* dst, const void* src) {
    uint32_t s = (uint32_t)__cvta_generic_to_shared(dst);
    asm volatile("cp.async.cg.shared.global [%0], [%1], 16;\n" :: "r"(s), "l"(src));
}

// ---------------- router: logits -> sigmoid -> grouped top-k -> normalized weights -----
__global__ __launch_bounds__(256) void router_kernel(
    const float* __restrict__ x, const float* __restrict__ gw,
    const float* __restrict__ bias, int* __restrict__ eid_out, float* __restrict__ tw_out)
{
    const int t = blockIdx.x;
    const float* xr = x + (size_t)t * H_;
    float acc[E_];
    #pragma unroll
    for (int e = 0; e < E_; ++e) acc[e] = 0.f;
    for (int h = threadIdx.x; h < H_; h += 256) {
        float xv = xr[h];
        #pragma unroll
        for (int e = 0; e < E_; ++e) acc[e] += xv * gw[e * H_ + h];
    }
    #pragma unroll
    for (int e = 0; e < E_; ++e)
        #pragma unroll
        for (int o = 16; o > 0; o >>= 1)
            acc[e] += __shfl_down_sync(0xffffffffu, acc[e], o);

    __shared__ float red[8][E_];
    const int warp = threadIdx.x >> 5, lane = threadIdx.x & 31;
    if (lane == 0)
        for (int e = 0; e < E_; ++e) red[warp][e] = acc[e];
    __syncthreads();

    if (threadIdx.x == 0) {
        float sc[E_], sb[E_];
        for (int e = 0; e < E_; ++e) {
            float l = 0.f;
            for (int w = 0; w < 8; ++w) l += red[w][e];
            sc[e] = 1.f / (1.f + expf(-l));
            sb[e] = sc[e] + bias[e];
        }
        // group score = sum of top-2 biased scores within each group of 4
        float gsc[4];
        for (int g = 0; g < 4; ++g) {
            float m1 = -1e30f, m2 = -1e30f;
            for (int j = 0; j < 4; ++j) {
                float v = sb[4*g + j];
                if (v > m1) { m2 = m1; m1 = v; } else if (v > m2) m2 = v;
            }
            gsc[g] = m1 + m2;
        }
        int gs0 = 0; float best = -1e30f;
        for (int g = 0; g < 4; ++g) if (gsc[g] > best) { best = gsc[g]; gs0 = g; }
        int gs1 = 0; best = -1e30f;
        for (int g = 0; g < 4; ++g) if (g != gs0 && gsc[g] > best) { best = gsc[g]; gs1 = g; }
        bool allow[E_];
        for (int e = 0; e < E_; ++e) { int g = e >> 2; allow[e] = (g == gs0 || g == gs1); }
        int ids[TK]; float ws[TK]; float wsum = 0.f;
        for (int k = 0; k < TK; ++k) {
            int be = 0; float bv = -1e30f;
            for (int e = 0; e < E_; ++e)
                if (allow[e] && sb[e] > bv) { bv = sb[e]; be = e; }
            allow[be] = false;
            ids[k] = be; ws[k] = sc[be]; wsum += sc[be];  // weights from UNbiased scores
        }
        const float inv = 1.f / wsum;
        for (int k = 0; k < TK; ++k) {
            eid_out[t*TK + k] = ids[k];
            tw_out [t*TK + k] = ws[k] * inv;
        }
    }
}

__global__ void build_lists(const int* __restrict__ ids, int* __restrict__ cnt,
                            int* __restrict__ rows) {
    int i = blockIdx.x * blockDim.x + threadIdx.x;
    if (i >= NA) return;
    int e = ids[i];
    int p = atomicAdd(&cnt[e], 1);
    rows[e * T_ + p] = i;   // assignment id; token = i>>2
}

// ---------------- grouped tf32 GEMM: 128x128x32 tiles, cp.async double-buffered --------
// rowmap: 0 = direct (A row = C row = local row, M = Mdirect)
//         1 = gather tokens (A row = rows[lr]>>2, C row = rows[lr], M = cnt[e])
//         2 = gather assignments (A row = C row = rows[lr], M = cnt[e])
__global__ __launch_bounds__(256)
void gemm_tf32(const float* __restrict__ A, int lda,
               const float* __restrict__ B, int ldb, long long strideBe,
               float* __restrict__ C, int ldc,
               const int* __restrict__ rows_base, const int* __restrict__ cnt,
               int rowmap, int Mdirect, int N, int K, float scale)
{
    extern __shared__ float smem[];
    const int e  = blockIdx.z;
    const int M  = (rowmap == 0) ? Mdirect : cnt[e];
    const int m0 = blockIdx.y * 128;
    if (M <= 0 || m0 >= M) return;
    const int n0 = blockIdx.x * 128;
    const int* rows = rows_base + e * T_;
    const float* Be = B + (long long)e * strideBe;

    float* As = smem;          // 2 stages * 128*32 floats (XOR-swizzled at float4 grain)
    float* Bs = smem + 8192;   // 2 stages * 32*128 floats

    const int tid  = threadIdx.x;
    const int warp = tid >> 5, lane = tid & 31;
    const int gid  = lane >> 2, t4 = lane & 3;
    const int wm   = (warp & 1) << 6;   // warp m-offset (2x4 warp grid -> 64x32 per warp)
    const int wn   = (warp >> 1) << 5;

    // precompute gathered A row per load slot (clamped; invalid rows never stored)
    long long aRow[4];
    #pragma unroll
    for (int p = 0; p < 4; ++p) {
        int r  = (tid + p*256) >> 3;
        int lr = m0 + r;
        if (lr >= M) lr = M - 1;
        if (rowmap == 0)        aRow[p] = lr;
        else if (rowmap == 1)   aRow[p] = rows[lr] >> 2;
        else                    aRow[p] = rows[lr];
    }

    float acc[4][4][4];
    #pragma unroll
    for (int mi = 0; mi < 4; ++mi)
        #pragma unroll
        for (int ni = 0; ni < 4; ++ni)
            #pragma unroll
            for (int q = 0; q < 4; ++q) acc[mi][ni][q] = 0.f;

    const int ktiles = K >> 5;

    auto issue = [&](int kt, int stage) {
        const int k0 = kt << 5;
        float* as = As + stage * 4096;
        float* bs = Bs + stage * 4096;
        #pragma unroll
        for (int p = 0; p < 4; ++p) {
            int idx = tid + p*256;
            int r = idx >> 3, c = idx & 7;              // 128 rows x 8 float4
            cp16(as + r*32 + ((c ^ (r & 7)) << 2),
                 A + aRow[p] * (long long)lda + k0 + (c << 2));
        }
        #pragma unroll
        for (int p = 0; p < 4; ++p) {
            int idx = tid + p*256;
            int r = idx >> 5, c = idx & 31;             // 32 k-rows x 32 float4
            cp16(bs + r*128 + ((c ^ (r & 7)) << 2),
                 Be + (long long)(k0 + r) * ldb + n0 + (c << 2));
        }
        asm volatile("cp.async.commit_group;\n");
    };

    issue(0, 0);
    for (int kt = 0; kt < ktiles; ++kt) {
        const int stage = kt & 1;
        if (kt + 1 < ktiles) {
            issue(kt + 1, stage ^ 1);
            asm volatile("cp.async.wait_group 1;\n");
        } else {
            asm volatile("cp.async.wait_group 0;\n");
        }
        __syncthreads();
        const float* as = As + stage * 4096;
        const float* bs = Bs + stage * 4096;
        #pragma unroll
        for (int kk = 0; kk < 4; ++kk) {
            uint32_t af[4][4], bf[4][2];
            const int k1 = (kk << 3) + t4, k2 = k1 + 4;
            #pragma unroll
            for (int mi = 0; mi < 4; ++mi) {
                const int ma = wm + (mi << 4) + gid, mb = ma + 8;
                af[mi][0] = f2tf32(as[ma*32 + (((k1 >> 2) ^ (ma & 7)) << 2) + (k1 & 3)]);
                af[mi][1] = f2tf32(as[mb*32 + (((k1 >> 2) ^ (mb & 7)) << 2) + (k1 & 3)]);
                af[mi][2] = f2tf32(as[ma*32 + (((k2 >> 2) ^ (ma & 7)) << 2) + (k2 & 3)]);
                af[mi][3] = f2tf32(as[mb*32 + (((k2 >> 2) ^ (mb & 7)) << 2) + (k2 & 3)]);
            }
            #pragma unroll
            for (int ni = 0; ni < 4; ++ni) {
                const int nn = wn + (ni << 3) + gid;
                bf[ni][0] = f2tf32(bs[k1*128 + (((nn >> 2) ^ (k1 & 7)) << 2) + (nn & 3)]);
                bf[ni][1] = f2tf32(bs[k2*128 + (((nn >> 2) ^ (k2 & 7)) << 2) + (nn & 3)]);
            }
            #pragma unroll
            for (int mi = 0; mi < 4; ++mi)
                #pragma unroll
                for (int ni = 0; ni < 4; ++ni)
                    mma8(acc[mi][ni], af[mi], bf[ni]);
        }
        __syncthreads();
    }

    // epilogue: scatter rows by assignment id (deterministic, no atomics)
    #pragma unroll
    for (int mi = 0; mi < 4; ++mi) {
        const int lr0 = m0 + wm + (mi << 4) + gid;
        const int lr1 = lr0 + 8;
        const bool v0 = lr0 < M, v1 = lr1 < M;
        long long cr0 = 0, cr1 = 0;
        if (rowmap == 0) { cr0 = lr0; cr1 = lr1; }
        else { if (v0) cr0 = rows[lr0]; if (v1) cr1 = rows[lr1]; }
        float* C0 = C + cr0 * (long long)ldc + n0 + wn;
        float* C1 = C + cr1 * (long long)ldc + n0 + wn;
        #pragma unroll
        for (int ni = 0; ni < 4; ++ni) {
            const int col = (ni << 3) + (t4 << 1);
            if (v0) { float2 v; v.x = acc[mi][ni][0]*scale; v.y = acc[mi][ni][1]*scale;
                      *(float2*)(C0 + col) = v; }
            if (v1) { float2 v; v.x = acc[mi][ni][2]*scale; v.y = acc[mi][ni][3]*scale;
                      *(float2*)(C1 + col) = v; }
        }
    }
}

// ---------------- elementwise kernels ---------------------------------------------------
__global__ void act_routed(const float* __restrict__ gu, const float* __restrict__ tw,
                           float* __restrict__ o) {
    const int a = blockIdx.y;
    const int i = blockIdx.x * blockDim.x + threadIdx.x;
    if (i >= I_) return;
    float g = gu[(size_t)a * (2*I_) + i];
    float u = gu[(size_t)a * (2*I_) + I_ + i];
    o[(size_t)a * I_ + i] = (g / (1.f + expf(-g))) * u * tw[a];
}
__global__ void act_shared_k(const float* __restrict__ gu, float* __restrict__ o) {
    const int t = blockIdx.y;
    const int i = blockIdx.x * blockDim.x + threadIdx.x;
    if (i >= IS_) return;
    float g = gu[(size_t)t * (2*IS_) + i];
    float u = gu[(size_t)t * (2*IS_) + IS_ + i];
    o[(size_t)t * IS_ + i] = (g / (1.f + expf(-g))) * u;
}
__global__ void combine_k(const float* __restrict__ routed, const float* __restrict__ sh,
                          float* __restrict__ out) {
    size_t idx = (size_t)blockIdx.x * blockDim.x + threadIdx.x;
    if (idx >= (size_t)T_ * H_) return;
    const int t = (int)(idx >> 11);
    const int h = (int)(idx & (H_ - 1));
    const float* rb = routed + (size_t)t * TK * H_ + h;
    out[idx] = rb[0] + rb[(size_t)H_] + rb[(size_t)2*H_] + rb[(size_t)3*H_] + sh[idx];
}

// ---------------- entry -----------------------------------------------------------------
extern "C" void kernel_launch(void* const* d_in, const int* in_sizes, int n_in,
                              void* d_out, int out_size) {
    const float* x    = (const float*)d_in[0];  // [1024, 2048]
    const float* gw   = (const float*)d_in[1];  // [16, 2048]
    const float* bias = (const float*)d_in[2];  // [16]
    const float* w_gu = (const float*)d_in[3];  // [16, 2048, 2816]
    const float* w_dn = (const float*)d_in[4];  // [16, 1408, 2048]
    const float* s_gu = (const float*)d_in[5];  // [2048, 5632]
    const float* s_dn = (const float*)d_in[6];  // [2816, 2048]
    float* out = (float*)d_out;                 // [1024, 2048] fp32

    float *pGU, *pACT, *pROUT, *pSGU, *pSACT, *pSH, *pTW;
    int *pEID, *pCNT, *pROWS;
    cudaGetSymbolAddress((void**)&pGU,   g_GU);
    cudaGetSymbolAddress((void**)&pACT,  g_ACT);
    cudaGetSymbolAddress((void**)&pROUT, g_ROUT);
    cudaGetSymbolAddress((void**)&pSGU,  g_SGU);
    cudaGetSymbolAddress((void**)&pSACT, g_SACT);
    cudaGetSymbolAddress((void**)&pSH,   g_SH);
    cudaGetSymbolAddress((void**)&pEID,  g_eid);
    cudaGetSymbolAddress((void**)&pTW,   g_tw);
    cudaGetSymbolAddress((void**)&pCNT,  g_cnt);
    cudaGetSymbolAddress((void**)&pROWS, g_rows);

    cudaFuncSetAttribute(gemm_tf32, cudaFuncAttributeMaxDynamicSharedMemorySize, 65536);

    // 1. router
    router_kernel<<<T_, 256>>>(x, gw, bias, pEID, pTW);
    // 2. per-expert token lists
    cudaMemsetAsync(pCNT, 0, E_ * sizeof(int));
    build_lists<<<NA / 256, 256>>>(pEID, pCNT, pROWS);
    // 3. routed gate_up: [cnt_e, 2048] @ [2048, 2816] -> GU (rows = assignment ids)
    {
        dim3 g((2*I_) / 128, T_ / 128, E_);
        gemm_tf32<<<g, 256, 65536>>>(x, H_, w_gu, 2*I_, (long long)H_ * (2*I_),
                                     pGU, 2*I_, pROWS, pCNT, 1, 0, 2*I_, H_, 1.0f);
    }
    // 4. silu(g)*u * routing weight
    {
        dim3 g((I_ + 255) / 256, NA);
        act_routed<<<g, 256>>>(pGU, pTW, pACT);
    }
    // 5. routed down: [cnt_e, 1408] @ [1408, 2048] * 2.5 -> ROUT (slot-indexed, no atomics)
    {
        dim3 g(H_ / 128, T_ / 128, E_);
        gemm_tf32<<<g, 256, 65536>>>(pACT, I_, w_dn, H_, (long long)I_ * H_,
                                     pROUT, H_, pROWS, pCNT, 2, 0, H_, I_, 2.5f);
    }
    // 6. shared gate_up: [1024, 2048] @ [2048, 5632]
    {
        dim3 g((2*IS_) / 128, T_ / 128, 1);
        gemm_tf32<<<g, 256, 65536>>>(x, H_, s_gu, 2*IS_, 0,
                                     pSGU, 2*IS_, pROWS, pCNT, 0, T_, 2*IS_, H_, 1.0f);
    }
    // 7. shared activation
    {
        dim3 g((IS_ + 255) / 256, T_);
        act_shared_k<<<g, 256>>>(pSGU, pSACT);
    }
    // 8. shared down: [1024, 2816] @ [2816, 2048]
    {
        dim3 g(H_ / 128, T_ / 128, 1);
        gemm_tf32<<<g, 256, 65536>>>(pSACT, IS_, s_dn, H_, 0,
                                     pSH, H_, pROWS, pCNT, 0, T_, H_, IS_, 1.0f);
    }
    // 9. out = sum_k routed[t,k,:] + shared[t,:]
    combine_k<<<(T_ * H_) / 256, 256>>>(pROUT, pSH, out);
}

// round 5
// speedup vs baseline: 1.1902x; 1.1902x over previous
#include <cuda_runtime.h>
#include <cuda_fp16.h>
#include <cstdint>
#include <math.h>

#define T_  1024
#define H_  2048
#define I_  1408
#define E_  16
#define IS_ 2816
#define TK  4
#define NA  (T_*TK)   // 4096 token-expert assignments

// ---------------- scratch (device globals; no allocation in kernel_launch) -------------
__device__ float g_ACT [(size_t)NA * I_];       // routed activation     [4096, 1408]
__device__ float g_ROUT[(size_t)NA * H_];       // routed down output    [4096, 2048]
__device__ float g_SACT[(size_t)T_ * IS_];      // shared activation     [1024, 2816]
__device__ float g_SH  [(size_t)T_ * H_];       // shared down output    [1024, 2048]
__device__ int   g_eid [NA];                    // expert id per assignment
__device__ float g_tw  [NA];                    // routing weight per assignment
__device__ int   g_cnt [E_];                    // tokens per expert
__device__ int   g_rows[E_ * T_];               // assignment ids grouped by expert

// ---------------- helpers ---------------------------------------------------------------
__device__ __forceinline__ uint32_t packh2(float lo, float hi) {
    __half2 h = __floats2half2_rn(lo, hi);      // .x (low 16) = lo
    return *reinterpret_cast<uint32_t*>(&h);
}
__device__ __forceinline__ void mma16(float* c, const uint32_t* a, const uint32_t* b) {
    asm volatile(
        "mma.sync.aligned.m16n8k16.row.col.f32.f16.f16.f32 "
        "{%0,%1,%2,%3}, {%4,%5,%6,%7}, {%8,%9}, {%0,%1,%2,%3};\n"
        : "+f"(c[0]), "+f"(c[1]), "+f"(c[2]), "+f"(c[3])
        : "r"(a[0]), "r"(a[1]), "r"(a[2]), "r"(a[3]), "r"(b[0]), "r"(b[1]));
}
__device__ __forceinline__ void cp16(void* dst, const void* src) {
    uint32_t s = (uint32_t)__cvta_generic_to_shared(dst);
    asm volatile("cp.async.cg.shared.global [%0], [%1], 16;\n" :: "r"(s), "l"(src));
}

// ---------------- router -----------------------------------------------------------------
__global__ __launch_bounds__(256) void router_kernel(
    const float* __restrict__ x, const float* __restrict__ gw,
    const float* __restrict__ bias, int* __restrict__ eid_out, float* __restrict__ tw_out)
{
    const int t = blockIdx.x;
    const float* xr = x + (size_t)t * H_;
    float acc[E_];
    #pragma unroll
    for (int e = 0; e < E_; ++e) acc[e] = 0.f;
    for (int h = threadIdx.x; h < H_; h += 256) {
        float xv = xr[h];
        #pragma unroll
        for (int e = 0; e < E_; ++e) acc[e] += xv * gw[e * H_ + h];
    }
    #pragma unroll
    for (int e = 0; e < E_; ++e)
        #pragma unroll
        for (int o = 16; o > 0; o >>= 1)
            acc[e] += __shfl_down_sync(0xffffffffu, acc[e], o);

    __shared__ float red[8][E_];
    const int warp = threadIdx.x >> 5, lane = threadIdx.x & 31;
    if (lane == 0)
        for (int e = 0; e < E_; ++e) red[warp][e] = acc[e];
    __syncthreads();

    if (threadIdx.x == 0) {
        float sc[E_], sb[E_];
        for (int e = 0; e < E_; ++e) {
            float l = 0.f;
            for (int w = 0; w < 8; ++w) l += red[w][e];
            sc[e] = 1.f / (1.f + expf(-l));
            sb[e] = sc[e] + bias[e];
        }
        float gsc[4];
        for (int g = 0; g < 4; ++g) {
            float m1 = -1e30f, m2 = -1e30f;
            for (int j = 0; j < 4; ++j) {
                float v = sb[4*g + j];
                if (v > m1) { m2 = m1; m1 = v; } else if (v > m2) m2 = v;
            }
            gsc[g] = m1 + m2;
        }
        int gs0 = 0; float best = -1e30f;
        for (int g = 0; g < 4; ++g) if (gsc[g] > best) { best = gsc[g]; gs0 = g; }
        int gs1 = 0; best = -1e30f;
        for (int g = 0; g < 4; ++g) if (g != gs0 && gsc[g] > best) { best = gsc[g]; gs1 = g; }
        bool allow[E_];
        for (int e = 0; e < E_; ++e) { int g = e >> 2; allow[e] = (g == gs0 || g == gs1); }
        int ids[TK]; float ws[TK]; float wsum = 0.f;
        for (int k = 0; k < TK; ++k) {
            int be = 0; float bv = -1e30f;
            for (int e = 0; e < E_; ++e)
                if (allow[e] && sb[e] > bv) { bv = sb[e]; be = e; }
            allow[be] = false;
            ids[k] = be; ws[k] = sc[be]; wsum += sc[be];
        }
        const float inv = 1.f / wsum;
        for (int k = 0; k < TK; ++k) {
            eid_out[t*TK + k] = ids[k];
            tw_out [t*TK + k] = ws[k] * inv;
        }
    }
}

__global__ void build_lists(const int* __restrict__ ids, int* __restrict__ cnt,
                            int* __restrict__ rows) {
    int i = blockIdx.x * blockDim.x + threadIdx.x;
    if (i >= NA) return;
    int e = ids[i];
    int p = atomicAdd(&cnt[e], 1);
    rows[e * T_ + p] = i;
}

// ---------------- fp16 grouped GEMM (legacy mma.sync m16n8k16) ---------------------------
// CTA 256 thr, tile 128(M)x128(N), K-tile 32. smem fp32, cp.async double-buffered,
// fragments converted fp32->half2 in registers.
// N layout: cols [0,64) from hcol0, cols [64,128) from hcol1 (hcol1 = halfBase + bx*colStep).
//   plain GEMM: colStep=128, halfBase=64  -> contiguous 128 cols at bx*128
//   fused GU:   colStep=64,  halfBase=I   -> 64 gate cols + 64 matching up cols
// rowmap: 0 direct (M=Mdirect) | 1 gather tokens (A=rows[lr]>>2, C=rows[lr]) | 2 gather asg.
// mode: 0 plain store *scale | 1 silu(gate)*up*tw[crow] -> C (64 cols) | 2 silu*up -> C
#define SMEMF 16896   // floats: staging epilogue needs 128*132 = 16896 > 16384 (stages)

__global__ __launch_bounds__(256)
void hgemm(const float* __restrict__ A, int lda,
           const float* __restrict__ B, int ldb, long long strideBe,
           float* __restrict__ C, int ldc,
           const int* __restrict__ rows_base, const int* __restrict__ cnt,
           const float* __restrict__ tw,
           int rowmap, int Mdirect, int K, int colStep, int halfBase,
           int mode, float scale)
{
    extern __shared__ float smem[];
    const int e  = blockIdx.z;
    const int M  = rowmap ? cnt[e] : Mdirect;
    const int m0 = blockIdx.y * 128;
    if (M <= 0 || m0 >= M) return;
    const int hcol0 = blockIdx.x * colStep;
    const int hcol1 = halfBase + blockIdx.x * colStep;
    const int* rows = rows_base + e * T_;
    const float* Be = B + (long long)e * strideBe;

    float* As = smem;          // 2 stages * 128*32 floats (XOR swizzle at float4 grain)
    float* Bs = smem + 8192;   // 2 stages * 32*128 floats

    const int tid  = threadIdx.x;
    const int warp = tid >> 5, lane = tid & 31;
    const int gid  = lane >> 2, t4 = lane & 3;
    const int wm   = (warp & 1) << 6;   // 2x4 warp grid, warp tile 64x32
    const int wn   = (warp >> 1) << 5;

    // per-thread load slots (constant across K tiles)
    long long srcA[4]; int dA[4];
    #pragma unroll
    for (int p = 0; p < 4; ++p) {
        int idx = tid + p*256;
        int r = idx >> 3, c = idx & 7;
        int lr = m0 + r; if (lr >= M) lr = M - 1;
        long long ar;
        if (rowmap == 0)      ar = lr;
        else { int a = rows[lr]; ar = (rowmap == 1) ? (a >> 2) : a; }
        srcA[p] = ar * lda + (c << 2);
        dA[p]   = r*32 + ((c ^ (r & 7)) << 2);
    }
    long long srcB[4]; int dB[4];
    #pragma unroll
    for (int p = 0; p < 4; ++p) {
        int idx = tid + p*256;
        int r = idx >> 5, c = idx & 31;
        int gcol = (c < 16) ? (hcol0 + (c << 2)) : (hcol1 + ((c - 16) << 2));
        srcB[p] = (long long)r * ldb + gcol;
        dB[p]   = r*128 + ((c ^ (r & 7)) << 2);
    }

    float acc[4][4][4];
    #pragma unroll
    for (int mi = 0; mi < 4; ++mi)
        #pragma unroll
        for (int ni = 0; ni < 4; ++ni)
            #pragma unroll
            for (int q = 0; q < 4; ++q) acc[mi][ni][q] = 0.f;

    const int ktiles = K >> 5;

    auto issue = [&](int kt, int stage) {
        const int k0 = kt << 5;
        float* as = As + stage * 4096;
        float* bs = Bs + stage * 4096;
        const float* Ak = A + k0;
        const float* Bk = Be + (long long)k0 * ldb;
        #pragma unroll
        for (int p = 0; p < 4; ++p) cp16(as + dA[p], Ak + srcA[p]);
        #pragma unroll
        for (int p = 0; p < 4; ++p) cp16(bs + dB[p], Bk + srcB[p]);
        asm volatile("cp.async.commit_group;\n");
    };

    issue(0, 0);
    for (int kt = 0; kt < ktiles; ++kt) {
        const int stage = kt & 1;
        if (kt + 1 < ktiles) {
            issue(kt + 1, stage ^ 1);
            asm volatile("cp.async.wait_group 1;\n");
        } else {
            asm volatile("cp.async.wait_group 0;\n");
        }
        __syncthreads();
        const float* as = As + stage * 4096;
        const float* bs = Bs + stage * 4096;
        #pragma unroll
        for (int kc = 0; kc < 2; ++kc) {
            const int ka = (kc << 4) + (t4 << 1);   // even k of low pair
            const int kb = ka + 8;
            uint32_t haf[4][4], hbf[4][2];
            #pragma unroll
            for (int mi = 0; mi < 4; ++mi) {
                const int r1 = wm + (mi << 4) + gid, r2 = r1 + 8;
                float2 v0 = *(const float2*)&as[r1*32 + (((ka >> 2) ^ (r1 & 7)) << 2) + (ka & 3)];
                float2 v1 = *(const float2*)&as[r2*32 + (((ka >> 2) ^ (r2 & 7)) << 2) + (ka & 3)];
                float2 v2 = *(const float2*)&as[r1*32 + (((kb >> 2) ^ (r1 & 7)) << 2) + (kb & 3)];
                float2 v3 = *(const float2*)&as[r2*32 + (((kb >> 2) ^ (r2 & 7)) << 2) + (kb & 3)];
                haf[mi][0] = packh2(v0.x, v0.y);
                haf[mi][1] = packh2(v1.x, v1.y);
                haf[mi][2] = packh2(v2.x, v2.y);
                haf[mi][3] = packh2(v3.x, v3.y);
            }
            #pragma unroll
            for (int ni = 0; ni < 4; ++ni) {
                const int n = wn + (ni << 3) + gid;
                const int gn = n >> 2, n3 = n & 3;
                float f0 = bs[ ka   *128 + ((gn ^ ( ka    & 7)) << 2) + n3];
                float f1 = bs[(ka+1)*128 + ((gn ^ ((ka+1) & 7)) << 2) + n3];
                float f2 = bs[ kb   *128 + ((gn ^ ( kb    & 7)) << 2) + n3];
                float f3 = bs[(kb+1)*128 + ((gn ^ ((kb+1) & 7)) << 2) + n3];
                hbf[ni][0] = packh2(f0, f1);
                hbf[ni][1] = packh2(f2, f3);
            }
            #pragma unroll
            for (int mi = 0; mi < 4; ++mi)
                #pragma unroll
                for (int ni = 0; ni < 4; ++ni)
                    mma16(acc[mi][ni], haf[mi], hbf[ni]);
        }
        __syncthreads();
    }

    if (mode == 0) {
        // direct store, cols mapped across the two halves
        #pragma unroll
        for (int mi = 0; mi < 4; ++mi) {
            const int lr0 = m0 + wm + (mi << 4) + gid;
            const int lr1 = lr0 + 8;
            const bool v0 = lr0 < M, v1 = lr1 < M;
            long long cr0 = 0, cr1 = 0;
            if (rowmap == 0) { cr0 = lr0; cr1 = lr1; }
            else { if (v0) cr0 = rows[lr0]; if (v1) cr1 = rows[lr1]; }
            #pragma unroll
            for (int ni = 0; ni < 4; ++ni) {
                const int cc = wn + (ni << 3) + (t4 << 1);
                const int gcol = (cc < 64) ? (hcol0 + cc) : (hcol1 + cc - 64);
                if (v0) { float2 v; v.x = acc[mi][ni][0]*scale; v.y = acc[mi][ni][1]*scale;
                          *(float2*)(C + cr0 * (long long)ldc + gcol) = v; }
                if (v1) { float2 v; v.x = acc[mi][ni][2]*scale; v.y = acc[mi][ni][3]*scale;
                          *(float2*)(C + cr1 * (long long)ldc + gcol) = v; }
            }
        }
    } else {
        // fused silu(gate)*up epilogue via smem staging (row stride 132 to dodge conflicts)
        #pragma unroll
        for (int mi = 0; mi < 4; ++mi) {
            const int r1 = wm + (mi << 4) + gid, r2 = r1 + 8;
            #pragma unroll
            for (int ni = 0; ni < 4; ++ni) {
                const int cc = wn + (ni << 3) + (t4 << 1);
                float2 v0; v0.x = acc[mi][ni][0]; v0.y = acc[mi][ni][1];
                float2 v1; v1.x = acc[mi][ni][2]; v1.y = acc[mi][ni][3];
                *(float2*)&smem[r1*132 + cc] = v0;
                *(float2*)&smem[r2*132 + cc] = v1;
            }
        }
        __syncthreads();
        const int r  = tid >> 1;
        const int ch = (tid & 1) << 5;
        const int lr = m0 + r;
        if (lr < M) {
            long long crow = rowmap ? rows[lr] : lr;
            const float f = (mode == 1) ? tw[crow] : 1.f;
            const float* gp = smem + r*132 + ch;
            const float* up = gp + 64;
            float* dst = C + crow * (long long)ldc + hcol0 + ch;
            #pragma unroll
            for (int q = 0; q < 8; ++q) {
                float4 gv = *(const float4*)(gp + (q << 2));
                float4 uv = *(const float4*)(up + (q << 2));
                float4 o;
                o.x = gv.x / (1.f + expf(-gv.x)) * uv.x * f;
                o.y = gv.y / (1.f + expf(-gv.y)) * uv.y * f;
                o.z = gv.z / (1.f + expf(-gv.z)) * uv.z * f;
                o.w = gv.w / (1.f + expf(-gv.w)) * uv.w * f;
                *(float4*)(dst + (q << 2)) = o;
            }
        }
    }
}

// ---------------- combine -----------------------------------------------------------------
__global__ void combine_k(const float* __restrict__ routed, const float* __restrict__ sh,
                          float* __restrict__ out) {
    size_t idx = (size_t)blockIdx.x * blockDim.x + threadIdx.x;
    if (idx >= (size_t)T_ * H_) return;
    const int t = (int)(idx >> 11);
    const int h = (int)(idx & (H_ - 1));
    const float* rb = routed + (size_t)t * TK * H_ + h;
    out[idx] = rb[0] + rb[(size_t)H_] + rb[(size_t)2*H_] + rb[(size_t)3*H_] + sh[idx];
}

// ---------------- entry --------------------------------------------------------------------
extern "C" void kernel_launch(void* const* d_in, const int* in_sizes, int n_in,
                              void* d_out, int out_size) {
    const float* x    = (const float*)d_in[0];  // [1024, 2048]
    const float* gw   = (const float*)d_in[1];  // [16, 2048]
    const float* bias = (const float*)d_in[2];  // [16]
    const float* w_gu = (const float*)d_in[3];  // [16, 2048, 2816]
    const float* w_dn = (const float*)d_in[4];  // [16, 1408, 2048]
    const float* s_gu = (const float*)d_in[5];  // [2048, 5632]
    const float* s_dn = (const float*)d_in[6];  // [2816, 2048]
    float* out = (float*)d_out;                 // [1024, 2048] fp32

    float *pACT, *pROUT, *pSACT, *pSH, *pTW;
    int *pEID, *pCNT, *pROWS;
    cudaGetSymbolAddress((void**)&pACT,  g_ACT);
    cudaGetSymbolAddress((void**)&pROUT, g_ROUT);
    cudaGetSymbolAddress((void**)&pSACT, g_SACT);
    cudaGetSymbolAddress((void**)&pSH,   g_SH);
    cudaGetSymbolAddress((void**)&pEID,  g_eid);
    cudaGetSymbolAddress((void**)&pTW,   g_tw);
    cudaGetSymbolAddress((void**)&pCNT,  g_cnt);
    cudaGetSymbolAddress((void**)&pROWS, g_rows);

    const int SMEM = SMEMF * 4;  // 67584 bytes
    cudaFuncSetAttribute(hgemm, cudaFuncAttributeMaxDynamicSharedMemorySize, SMEM);

    // 1. router
    router_kernel<<<T_, 256>>>(x, gw, bias, pEID, pTW);
    // 2. per-expert assignment lists
    cudaMemsetAsync(pCNT, 0, E_ * sizeof(int));
    build_lists<<<NA / 256, 256>>>(pEID, pCNT, pROWS);
    // 3. routed gate_up fused: 64 gate + 64 up cols per CTA -> silu*up*tw -> ACT
    {
        dim3 g(I_ / 64, T_ / 128, E_);
        hgemm<<<g, 256, SMEM>>>(x, H_, w_gu, 2*I_, (long long)H_ * (2*I_),
                                pACT, I_, pROWS, pCNT, pTW,
                                /*rowmap*/1, 0, /*K*/H_, /*colStep*/64, /*halfBase*/I_,
                                /*mode*/1, 1.0f);
    }
    // 4. routed down * 2.5 -> ROUT slots (deterministic scatter, no atomics)
    {
        dim3 g(H_ / 128, T_ / 128, E_);
        hgemm<<<g, 256, SMEM>>>(pACT, I_, w_dn, H_, (long long)I_ * H_,
                                pROUT, H_, pROWS, pCNT, pTW,
                                /*rowmap*/2, 0, /*K*/I_, /*colStep*/128, /*halfBase*/64,
                                /*mode*/0, 2.5f);
    }
    // 5. shared gate_up fused -> SACT
    {
        dim3 g(IS_ / 64, T_ / 128, 1);
        hgemm<<<g, 256, SMEM>>>(x, H_, s_gu, 2*IS_, 0,
                                pSACT, IS_, pROWS, pCNT, pTW,
                                /*rowmap*/0, T_, /*K*/H_, /*colStep*/64, /*halfBase*/IS_,
                                /*mode*/2, 1.0f);
    }
    // 6. shared down -> SH
    {
        dim3 g(H_ / 128, T_ / 128, 1);
        hgemm<<<g, 256, SMEM>>>(pSACT, IS_, s_dn, H_, 0,
                                pSH, H_, pROWS, pCNT, pTW,
                                /*rowmap*/0, T_, /*K*/IS_, /*colStep*/128, /*halfBase*/64,
                                /*mode*/0, 1.0f);
    }
    // 7. out = sum_k routed[t,k,:] + shared[t,:]
    combine_k<<<(T_ * H_) / 256, 256>>>(pROUT, pSH, out);
}

// round 8
// speedup vs baseline: 1.7028x; 1.4307x over previous
#include <cuda_runtime.h>
#include <cuda_fp16.h>
#include <cstdint>
#include <math.h>

#define T_  1024
#define H_  2048
#define I_  1408
#define E_  16
#define IS_ 2816
#define TK  4
#define NA  (T_*TK)   // 4096 token-expert assignments

// ---------------- scratch (device globals) ----------------------------------------------
__device__ __half g_XH   [(size_t)T_ * H_];
__device__ __half g_WGUH [(size_t)E_ * H_ * (2*I_)];
__device__ __half g_WDNH [(size_t)E_ * I_ * H_];
__device__ __half g_SGUH [(size_t)H_ * (2*IS_)];
__device__ __half g_SDNH [(size_t)IS_ * H_];
__device__ __half g_ACTH [(size_t)NA * I_];
__device__ __half g_SACTH[(size_t)T_ * IS_];
__device__ float  g_ROUT [(size_t)NA * H_];
__device__ float  g_SH   [(size_t)T_ * H_];
__device__ int    g_eid [NA];
__device__ float  g_tw  [NA];
__device__ int    g_cnt [E_];
__device__ int    g_rows[E_ * T_];

// ---------------- helpers ---------------------------------------------------------------
__device__ __forceinline__ uint32_t smem_u32(const void* p) {
    uint32_t a;
    asm("{ .reg .u64 t; cvta.to.shared.u64 t, %1; cvt.u32.u64 %0, t; }" : "=r"(a) : "l"(p));
    return a;
}
__device__ __forceinline__ void cp16s(uint32_t dst, const void* src) {
    asm volatile("cp.async.cg.shared.global [%0], [%1], 16;\n" :: "r"(dst), "l"(src));
}
__device__ __forceinline__ void mma16(float* c, const uint32_t* a, const uint32_t* b) {
    asm volatile(
        "mma.sync.aligned.m16n8k16.row.col.f32.f16.f16.f32 "
        "{%0,%1,%2,%3}, {%4,%5,%6,%7}, {%8,%9}, {%0,%1,%2,%3};\n"
        : "+f"(c[0]), "+f"(c[1]), "+f"(c[2]), "+f"(c[3])
        : "r"(a[0]), "r"(a[1]), "r"(a[2]), "r"(a[3]), "r"(b[0]), "r"(b[1]));
}
__device__ __forceinline__ void ldmA(uint32_t* r, uint32_t addr) {
    asm volatile("ldmatrix.sync.aligned.m8n8.x4.shared.b16 {%0,%1,%2,%3}, [%4];"
        : "=r"(r[0]), "=r"(r[1]), "=r"(r[2]), "=r"(r[3]) : "r"(addr));
}
__device__ __forceinline__ void ldmBT(uint32_t* r, uint32_t addr) {
    asm volatile("ldmatrix.sync.aligned.m8n8.x4.trans.shared.b16 {%0,%1,%2,%3}, [%4];"
        : "=r"(r[0]), "=r"(r[1]), "=r"(r[2]), "=r"(r[3]) : "r"(addr));
}
__device__ __forceinline__ uint32_t packh2(float lo, float hi) {
    __half2 h = __floats2half2_rn(lo, hi);
    return *reinterpret_cast<uint32_t*>(&h);
}

// ---------------- fp32 -> fp16 conversion (16 floats / thread, exact-size grids) --------
__global__ void f2h(const float4* __restrict__ in, uint2* __restrict__ out) {
    size_t i = ((size_t)blockIdx.x * 256 + threadIdx.x) * 4;
    #pragma unroll
    for (int q = 0; q < 4; ++q) {
        float4 v = in[i + q];
        __half2 a = __floats2half2_rn(v.x, v.y);
        __half2 b = __floats2half2_rn(v.z, v.w);
        uint2 o;
        o.x = *reinterpret_cast<uint32_t*>(&a);
        o.y = *reinterpret_cast<uint32_t*>(&b);
        out[i + q] = o;
    }
}

// ---------------- router -----------------------------------------------------------------
__global__ __launch_bounds__(256) void router_kernel(
    const float* __restrict__ x, const float* __restrict__ gw,
    const float* __restrict__ bias, int* __restrict__ eid_out, float* __restrict__ tw_out)
{
    const int t = blockIdx.x;
    const float* xr = x + (size_t)t * H_;
    float acc[E_];
    #pragma unroll
    for (int e = 0; e < E_; ++e) acc[e] = 0.f;
    for (int h = threadIdx.x; h < H_; h += 256) {
        float xv = xr[h];
        #pragma unroll
        for (int e = 0; e < E_; ++e) acc[e] += xv * gw[e * H_ + h];
    }
    #pragma unroll
    for (int e = 0; e < E_; ++e)
        #pragma unroll
        for (int o = 16; o > 0; o >>= 1)
            acc[e] += __shfl_down_sync(0xffffffffu, acc[e], o);

    __shared__ float red[8][E_];
    const int warp = threadIdx.x >> 5, lane = threadIdx.x & 31;
    if (lane == 0)
        for (int e = 0; e < E_; ++e) red[warp][e] = acc[e];
    __syncthreads();

    if (threadIdx.x == 0) {
        float sc[E_], sb[E_];
        for (int e = 0; e < E_; ++e) {
            float l = 0.f;
            for (int w = 0; w < 8; ++w) l += red[w][e];
            sc[e] = 1.f / (1.f + expf(-l));
            sb[e] = sc[e] + bias[e];
        }
        float gsc[4];
        for (int g = 0; g < 4; ++g) {
            float m1 = -1e30f, m2 = -1e30f;
            for (int j = 0; j < 4; ++j) {
                float v = sb[4*g + j];
                if (v > m1) { m2 = m1; m1 = v; } else if (v > m2) m2 = v;
            }
            gsc[g] = m1 + m2;
        }
        int gs0 = 0; float best = -1e30f;
        for (int g = 0; g < 4; ++g) if (gsc[g] > best) { best = gsc[g]; gs0 = g; }
        int gs1 = 0; best = -1e30f;
        for (int g = 0; g < 4; ++g) if (g != gs0 && gsc[g] > best) { best = gsc[g]; gs1 = g; }
        bool allow[E_];
        for (int e = 0; e < E_; ++e) { int g = e >> 2; allow[e] = (g == gs0 || g == gs1); }
        int ids[TK]; float ws[TK]; float wsum = 0.f;
        for (int k = 0; k < TK; ++k) {
            int be = 0; float bv = -1e30f;
            for (int e = 0; e < E_; ++e)
                if (allow[e] && sb[e] > bv) { bv = sb[e]; be = e; }
            allow[be] = false;
            ids[k] = be; ws[k] = sc[be]; wsum += sc[be];
        }
        const float inv = 1.f / wsum;
        for (int k = 0; k < TK; ++k) {
            eid_out[t*TK + k] = ids[k];
            tw_out [t*TK + k] = ws[k] * inv;
        }
    }
}

__global__ void build_lists(const int* __restrict__ ids, int* __restrict__ cnt,
                            int* __restrict__ rows) {
    int i = blockIdx.x * blockDim.x + threadIdx.x;
    if (i >= NA) return;
    int e = ids[i];
    int p = atomicAdd(&cnt[e], 1);
    rows[e * T_ + p] = i;
}

// ---------------- fp16 ldmatrix HGEMM -----------------------------------------------------
// CTA 256 thr (8 warps, 2(M)x4(N)), tile 128x128, K-tile 64, fp16 smem double-buffered.
// A tile: 128 rows x 64 halves (8x16B chunks, chunk c at phys c^(m&7)).
// B tile: 64 k-rows x 128 halves (16 chunks, chunk cn at phys cn^(k&7)).
// N layout: cols [0,64) from hcol0, [64,128) from hcol1 = halfBase + bx*colStep.
// rowmap: 0 direct | 1 gather tokens (A=rows[lr]>>2, C=rows[lr]) | 2 gather assignments.
// mode: 0 plain fp32 store *scale | 1 silu(g)*u*tw -> half C | 2 silu(g)*u -> half C
#define SMEM_BYTES 67584   // max(2*32768 stages, 128*132*4 staging)

__global__ __launch_bounds__(256, 2)
void hgemm(const __half* __restrict__ A, int lda,
           const __half* __restrict__ B, int ldb, long long strideBe,
           void* __restrict__ Cv, int ldc,
           const int* __restrict__ rows_base, const int* __restrict__ cnt,
           const float* __restrict__ tw,
           int rowmap, int Mdirect, int K, int colStep, int halfBase,
           int mode, float scale)
{
    extern __shared__ char smem[];
    const uint32_t sb = smem_u32(smem);
    const int e  = blockIdx.z;
    const int M  = rowmap ? cnt[e] : Mdirect;
    const int m0 = blockIdx.y * 128;
    if (M <= 0 || m0 >= M) return;
    const int hcol0 = blockIdx.x * colStep;
    const int hcol1 = halfBase + blockIdx.x * colStep;
    const int* rows = rows_base + e * T_;
    const __half* Be = B + (long long)e * strideBe;

    const int tid = threadIdx.x, warp = tid >> 5, lane = tid & 31;
    const int wm = (warp & 1) << 6, wn = (warp >> 1) << 5;
    const int lane15 = lane & 15, hi = lane >> 4;
    const int gid = lane >> 2, t4 = lane & 3;

    // cp.async slots (constant across K)
    int srcA[4]; uint32_t dA[4];
    #pragma unroll
    for (int p = 0; p < 4; ++p) {
        int idx = tid + p * 256;
        int m = idx >> 3, c = idx & 7;
        int lr = m0 + m; if (lr >= M) lr = M - 1;
        int ar;
        if (rowmap == 0)      ar = lr;
        else { int a = rows[lr]; ar = (rowmap == 1) ? (a >> 2) : a; }
        srcA[p] = ar * lda + (c << 3);
        dA[p]   = (uint32_t)(m * 128 + ((c ^ (m & 7)) << 4));
    }
    int srcB[4]; uint32_t dB[4];
    #pragma unroll
    for (int p = 0; p < 4; ++p) {
        int idx = tid + p * 256;
        int k = idx >> 4, cn = idx & 15;
        int c128 = cn << 3;
        int gcol = (c128 < 64) ? (hcol0 + c128) : (hcol1 + c128 - 64);
        srcB[p] = k * ldb + gcol;
        dB[p]   = (uint32_t)(k * 256 + ((cn ^ (k & 7)) << 4));
    }

    // ldmatrix lane addressing precompute
    uint32_t amul[4]; int axor[4];
    #pragma unroll
    for (int mi = 0; mi < 4; ++mi) {
        int m = wm + mi * 16 + lane15;
        amul[mi] = (uint32_t)(m * 128);
        axor[mi] = m & 7;
    }
    uint32_t bLane[2];
    #pragma unroll
    for (int nj = 0; nj < 2; ++nj) {
        int basecn = (wn >> 3) + nj * 2;
        bLane[nj] = (uint32_t)(lane15 * 256 + (((basecn + hi) ^ (lane & 7)) << 4));
    }

    float acc[4][4][4];
    #pragma unroll
    for (int mi = 0; mi < 4; ++mi)
        #pragma unroll
        for (int ni = 0; ni < 4; ++ni)
            #pragma unroll
            for (int q = 0; q < 4; ++q) acc[mi][ni][q] = 0.f;

    const int ktiles = K >> 6;

    auto issue = [&](int kt, int stage) {
        const int k0 = kt << 6;
        const __half* Ak = A + k0;
        const __half* Bk = Be + (long long)k0 * ldb;
        const uint32_t aS = sb + stage * 32768;
        const uint32_t bS = aS + 16384;
        #pragma unroll
        for (int p = 0; p < 4; ++p) cp16s(aS + dA[p], Ak + srcA[p]);
        #pragma unroll
        for (int p = 0; p < 4; ++p) cp16s(bS + dB[p], Bk + srcB[p]);
        asm volatile("cp.async.commit_group;\n");
    };

    issue(0, 0);
    for (int kt = 0; kt < ktiles; ++kt) {
        const int stage = kt & 1;
        if (kt + 1 < ktiles) {
            issue(kt + 1, stage ^ 1);
            asm volatile("cp.async.wait_group 1;\n");
        } else {
            asm volatile("cp.async.wait_group 0;\n");
        }
        __syncthreads();
        const uint32_t aS = sb + stage * 32768;
        const uint32_t bS = aS + 16384;
        #pragma unroll
        for (int ks = 0; ks < 4; ++ks) {
            uint32_t af[4][4];
            #pragma unroll
            for (int mi = 0; mi < 4; ++mi)
                ldmA(af[mi], aS + amul[mi] +
                     (uint32_t)(((((ks << 1) | hi)) ^ axor[mi]) << 4));
            uint32_t bf0[4], bf1[4];
            ldmBT(bf0, bS + bLane[0] + (ks << 12));
            ldmBT(bf1, bS + bLane[1] + (ks << 12));
            #pragma unroll
            for (int mi = 0; mi < 4; ++mi) {
                mma16(acc[mi][0], af[mi], bf0 + 0);
                mma16(acc[mi][1], af[mi], bf0 + 2);
                mma16(acc[mi][2], af[mi], bf1 + 0);
                mma16(acc[mi][3], af[mi], bf1 + 2);
            }
        }
        __syncthreads();
    }

    if (mode == 0) {
        float* C = (float*)Cv;
        #pragma unroll
        for (int mi = 0; mi < 4; ++mi) {
            const int lr0 = m0 + wm + (mi << 4) + gid;
            const int lr1 = lr0 + 8;
            const bool v0 = lr0 < M, v1 = lr1 < M;
            long long cr0 = 0, cr1 = 0;
            if (rowmap == 0) { cr0 = lr0; cr1 = lr1; }
            else { if (v0) cr0 = rows[lr0]; if (v1) cr1 = rows[lr1]; }
            #pragma unroll
            for (int ni = 0; ni < 4; ++ni) {
                const int cc = wn + (ni << 3) + (t4 << 1);
                const int gcol = (cc < 64) ? (hcol0 + cc) : (hcol1 + cc - 64);
                if (v0) { float2 v; v.x = acc[mi][ni][0]*scale; v.y = acc[mi][ni][1]*scale;
                          *(float2*)(C + cr0 * (long long)ldc + gcol) = v; }
                if (v1) { float2 v; v.x = acc[mi][ni][2]*scale; v.y = acc[mi][ni][3]*scale;
                          *(float2*)(C + cr1 * (long long)ldc + gcol) = v; }
            }
        }
    } else {
        // fused silu(gate)*up epilogue via smem staging (stride 132 floats)
        float* stage = (float*)smem;
        #pragma unroll
        for (int mi = 0; mi < 4; ++mi) {
            const int r1 = wm + (mi << 4) + gid, r2 = r1 + 8;
            #pragma unroll
            for (int ni = 0; ni < 4; ++ni) {
                const int cc = wn + (ni << 3) + (t4 << 1);
                float2 v0; v0.x = acc[mi][ni][0]; v0.y = acc[mi][ni][1];
                float2 v1; v1.x = acc[mi][ni][2]; v1.y = acc[mi][ni][3];
                *(float2*)&stage[r1*132 + cc] = v0;
                *(float2*)&stage[r2*132 + cc] = v1;
            }
        }
        __syncthreads();
        const int r  = tid >> 1;
        const int ch = (tid & 1) << 5;
        const int lr = m0 + r;
        if (lr < M) {
            long long crow = rowmap ? rows[lr] : lr;
            const float f = (mode == 1) ? tw[crow] : 1.f;
            const float* gp = stage + r*132 + ch;
            const float* up = gp + 64;
            __half* dst = (__half*)Cv + crow * (long long)ldc + hcol0 + ch;
            #pragma unroll
            for (int q = 0; q < 4; ++q) {
                float4 g0 = *(const float4*)(gp + (q << 3));
                float4 g1 = *(const float4*)(gp + (q << 3) + 4);
                float4 u0 = *(const float4*)(up + (q << 3));
                float4 u1 = *(const float4*)(up + (q << 3) + 4);
                float o0 = g0.x / (1.f + expf(-g0.x)) * u0.x * f;
                float o1 = g0.y / (1.f + expf(-g0.y)) * u0.y * f;
                float o2 = g0.z / (1.f + expf(-g0.z)) * u0.z * f;
                float o3 = g0.w / (1.f + expf(-g0.w)) * u0.w * f;
                float o4 = g1.x / (1.f + expf(-g1.x)) * u1.x * f;
                float o5 = g1.y / (1.f + expf(-g1.y)) * u1.y * f;
                float o6 = g1.z / (1.f + expf(-g1.z)) * u1.z * f;
                float o7 = g1.w / (1.f + expf(-g1.w)) * u1.w * f;
                uint4 o;
                o.x = packh2(o0, o1); o.y = packh2(o2, o3);
                o.z = packh2(o4, o5); o.w = packh2(o6, o7);
                *(uint4*)(dst + (q << 3)) = o;
            }
        }
    }
}

// ---------------- combine (vectorized) -----------------------------------------------------
__global__ void combine_k(const float4* __restrict__ routed, const float4* __restrict__ sh,
                          float4* __restrict__ out) {
    int idx = blockIdx.x * blockDim.x + threadIdx.x;          // over T*H/4
    if (idx >= T_ * H_ / 4) return;
    const int t = idx >> 9;                                    // H/4 = 512
    const size_t b = ((size_t)t * TK) * 512 + (idx & 511);
    float4 a0 = routed[b], a1 = routed[b + 512], a2 = routed[b + 1024], a3 = routed[b + 1536];
    float4 s = sh[idx];
    float4 o;
    o.x = a0.x + a1.x + a2.x + a3.x + s.x;
    o.y = a0.y + a1.y + a2.y + a3.y + s.y;
    o.z = a0.z + a1.z + a2.z + a3.z + s.z;
    o.w = a0.w + a1.w + a2.w + a3.w + s.w;
    out[idx] = o;
}

// ---------------- entry ---------------------------------------------------------------------
extern "C" void kernel_launch(void* const* d_in, const int* in_sizes, int n_in,
                              void* d_out, int out_size) {
    const float* x    = (const float*)d_in[0];  // [1024, 2048]
    const float* gw   = (const float*)d_in[1];  // [16, 2048]
    const float* bias = (const float*)d_in[2];  // [16]
    const float* w_gu = (const float*)d_in[3];  // [16, 2048, 2816]
    const float* w_dn = (const float*)d_in[4];  // [16, 1408, 2048]
    const float* s_gu = (const float*)d_in[5];  // [2048, 5632]
    const float* s_dn = (const float*)d_in[6];  // [2816, 2048]
    float* out = (float*)d_out;                 // [1024, 2048] fp32

    __half *pXH, *pWGUH, *pWDNH, *pSGUH, *pSDNH, *pACTH, *pSACTH;
    float *pROUT, *pSH, *pTW;
    int *pEID, *pCNT, *pROWS;
    cudaGetSymbolAddress((void**)&pXH,    g_XH);
    cudaGetSymbolAddress((void**)&pWGUH,  g_WGUH);
    cudaGetSymbolAddress((void**)&pWDNH,  g_WDNH);
    cudaGetSymbolAddress((void**)&pSGUH,  g_SGUH);
    cudaGetSymbolAddress((void**)&pSDNH,  g_SDNH);
    cudaGetSymbolAddress((void**)&pACTH,  g_ACTH);
    cudaGetSymbolAddress((void**)&pSACTH, g_SACTH);
    cudaGetSymbolAddress((void**)&pROUT,  g_ROUT);
    cudaGetSymbolAddress((void**)&pSH,    g_SH);
    cudaGetSymbolAddress((void**)&pEID,   g_eid);
    cudaGetSymbolAddress((void**)&pTW,    g_tw);
    cudaGetSymbolAddress((void**)&pCNT,   g_cnt);
    cudaGetSymbolAddress((void**)&pROWS,  g_rows);

    cudaFuncSetAttribute(hgemm, cudaFuncAttributeMaxDynamicSharedMemorySize, SMEM_BYTES);

    // 0. fp32 -> fp16 conversions (sizes all divisible by 16*256 floats)
    f2h<<<  512, 256>>>((const float4*)x,    (uint2*)pXH);
    f2h<<<22528, 256>>>((const float4*)w_gu, (uint2*)pWGUH);
    f2h<<<11264, 256>>>((const float4*)w_dn, (uint2*)pWDNH);
    f2h<<< 2816, 256>>>((const float4*)s_gu, (uint2*)pSGUH);
    f2h<<< 1408, 256>>>((const float4*)s_dn, (uint2*)pSDNH);

    // 1. router
    router_kernel<<<T_, 256>>>(x, gw, bias, pEID, pTW);
    // 2. per-expert assignment lists
    cudaMemsetAsync(pCNT, 0, E_ * sizeof(int));
    build_lists<<<NA / 256, 256>>>(pEID, pCNT, pROWS);
    // 3. routed gate_up fused: 64 gate + 64 up cols -> silu*up*tw -> ACTH (half)
    {
        dim3 g(I_ / 64, T_ / 128, E_);
        hgemm<<<g, 256, SMEM_BYTES>>>(pXH, H_, pWGUH, 2*I_, (long long)H_ * (2*I_),
                                      pACTH, I_, pROWS, pCNT, pTW,
                                      1, 0, H_, 64, I_, 1, 1.0f);
    }
    // 4. routed down * 2.5 -> ROUT slots (fp32, deterministic scatter)
    {
        dim3 g(H_ / 128, T_ / 128, E_);
        hgemm<<<g, 256, SMEM_BYTES>>>(pACTH, I_, pWDNH, H_, (long long)I_ * H_,
                                      pROUT, H_, pROWS, pCNT, pTW,
                                      2, 0, I_, 128, 64, 0, 2.5f);
    }
    // 5. shared gate_up fused -> SACTH (half)
    {
        dim3 g(IS_ / 64, T_ / 128, 1);
        hgemm<<<g, 256, SMEM_BYTES>>>(pXH, H_, pSGUH, 2*IS_, 0,
                                      pSACTH, IS_, pROWS, pCNT, pTW,
                                      0, T_, H_, 64, IS_, 2, 1.0f);
    }
    // 6. shared down -> SH (fp32)
    {
        dim3 g(H_ / 128, T_ / 128, 1);
        hgemm<<<g, 256, SMEM_BYTES>>>(pSACTH, IS_, pSDNH, H_, 0,
                                      pSH, H_, pROWS, pCNT, pTW,
                                      0, T_, IS_, 128, 64, 0, 1.0f);
    }
    // 7. out = sum_k routed[t,k,:] + shared[t,:]
    combine_k<<<(T_ * H_ / 4 + 255) / 256, 256>>>((const float4*)pROUT, (const float4*)pSH,
                                                  (float4*)out);
}